// round 11
// baseline (speedup 1.0000x reference)
#include <cuda_runtime.h>
#include <cuda_fp16.h>
#include <cstdint>

// Problem dims
#define KTOT 8192
#define MOUT 2000
#define NOUT 2000
#define NPAD 2048

// Sparse compaction geometry
#define GR 32                 // rows per m-group
#define NGRP 64               // 2048/32 groups (63 = all-pad -> empty)
#define CAPB 1344             // max kept 4-wide k-blocks per group (multiple of 16; mean~1166, +8 sigma)
#define NCHMAX (CAPB / 16)    // 84 chunks of 64 k
#define BN 256
#define NTILES_N 8
#define NTILE_TOT (NGRP * NTILES_N)   // 512

// GEMM smem staging
#define STAGES 3
#define A_ST 4096                       // 32 rows x 128B (one Wc chunk)
#define B_ST 32768                      // 64 k-rows x 512B (256 n fp16)
#define STG_BYTES (A_ST + B_ST)         // 36864
#define SMEM_TOTAL (STAGES * STG_BYTES) // 110592 -> 2 CTAs/SM

// Scratch
__device__ __align__(256) __half g_Xn[(size_t)KTOT * NPAD];             // [k][n] fp16
__device__ __align__(256) __half g_Wc[(size_t)NGRP * NCHMAX * 2048];    // pre-swizzled 4KB chunks
__device__ int g_klist[NGRP * CAPB];
__device__ int g_kcnt[NGRP];
__device__ int g_nch[NGRP];
__device__ int g_ctr;

// ---------------- PTX helpers ----------------
__device__ __forceinline__ uint32_t smem_u32(const void* p) {
    uint32_t a;
    asm("{ .reg .u64 t; cvta.to.shared.u64 t, %1; cvt.u32.u64 %0, t; }" : "=r"(a) : "l"(p));
    return a;
}

__device__ __forceinline__ void cp16(uint32_t s, const void* g) {
    asm volatile("cp.async.cg.shared.global [%0], [%1], 16;" :: "r"(s), "l"(g));
}

__device__ __forceinline__ void cp_commit() {
    asm volatile("cp.async.commit_group;" ::: "memory");
}

template <int N>
__device__ __forceinline__ void cp_wait() {
    asm volatile("cp.async.wait_group %0;" :: "n"(N) : "memory");
}

__device__ __forceinline__ void ldsm_x4(uint32_t* r, uint32_t addr) {
    asm volatile("ldmatrix.sync.aligned.m8n8.x4.shared.b16 {%0,%1,%2,%3}, [%4];"
                 : "=r"(r[0]), "=r"(r[1]), "=r"(r[2]), "=r"(r[3]) : "r"(addr));
}

__device__ __forceinline__ void ldsm_x4_t(uint32_t* r, uint32_t addr) {
    asm volatile("ldmatrix.sync.aligned.m8n8.x4.trans.shared.b16 {%0,%1,%2,%3}, [%4];"
                 : "=r"(r[0]), "=r"(r[1]), "=r"(r[2]), "=r"(r[3]) : "r"(addr));
}

__device__ __forceinline__ void mma16816(float* c, const uint32_t* a, const uint32_t* b) {
    asm volatile(
        "mma.sync.aligned.m16n8k16.row.col.f32.f16.f16.f32 "
        "{%0,%1,%2,%3}, {%4,%5,%6,%7}, {%8,%9}, {%0,%1,%2,%3};"
        : "+f"(c[0]), "+f"(c[1]), "+f"(c[2]), "+f"(c[3])
        : "r"(a[0]), "r"(a[1]), "r"(a[2]), "r"(a[3]), "r"(b[0]), "r"(b[1]));
}

// ---------------- K1: per-group kept-block lists (deterministic) ----------------
__global__ void __launch_bounds__(256) build_klist_kernel(const float* __restrict__ W) {
    const int mg = blockIdx.x;
    const int tid = threadIdx.x;
    __shared__ unsigned char flg[2048];
    __shared__ int tsum[256];
    __shared__ int totalS;

    const int row0 = mg * GR;
    int rowsN = MOUT - row0;
    if (rowsN > GR) rowsN = GR;
    if (rowsN < 0) rowsN = 0;

    int cnt8 = 0;
#pragma unroll
    for (int u = 0; u < 8; u++) {
        const int cb = tid * 8 + u;
        bool kept = false;
        for (int r = 0; r < rowsN && !kept; r++) {
            const float4 v = *reinterpret_cast<const float4*>(
                W + (size_t)(row0 + r) * KTOT + (size_t)cb * 4);
            kept = (v.x != 0.0f) || (v.y != 0.0f) || (v.z != 0.0f) || (v.w != 0.0f);
        }
        flg[tid * 8 + u] = kept ? 1 : 0;
        cnt8 += kept ? 1 : 0;
    }
    tsum[tid] = cnt8;
    __syncthreads();
    if (tid == 0) {
        int a = 0;
        for (int i = 0; i < 256; i++) { int v = tsum[i]; tsum[i] = a; a += v; }
        totalS = a;
    }
    __syncthreads();

    int pos = tsum[tid];
#pragma unroll
    for (int u = 0; u < 8; u++) {
        if (flg[tid * 8 + u] && pos < CAPB) g_klist[mg * CAPB + pos++] = tid * 8 + u;
        else if (flg[tid * 8 + u]) pos++;
    }

    if (tid == 0) {
        int cnt = totalS;
        if (cnt > CAPB) cnt = CAPB;
        int pad = (cnt + 15) & ~15;
        if (pad > CAPB) pad = CAPB;
        g_kcnt[mg] = cnt;
        g_nch[mg] = pad >> 4;
        for (int i = cnt; i < pad; i++) g_klist[mg * CAPB + i] = 0;  // valid dummy
        if (mg == 0) g_ctr = 0;
    }
}

// ---------------- K2: compact W into pre-swizzled fp16 chunks ----------------
// Chunk (mg, c): 32 rows x 64 k (blocks klist[c*16 .. c*16+15]), SW128-style swizzle.
__global__ void __launch_bounds__(256) fill_wc_kernel(const float* __restrict__ W) {
    const int c = blockIdx.x;
    const int mg = blockIdx.y;
    if (c >= g_nch[mg]) return;
    const int cnt = g_kcnt[mg];
    const int tid = threadIdx.x;
    const int row = tid >> 3;          // 0..31
    const int kseg = (tid & 7) * 8;    // 8 halfs
    const int m = mg * GR + row;

    const int s0 = c * 16 + (kseg >> 2);
    float v[8];
#pragma unroll
    for (int p = 0; p < 2; p++) {
        const int s = s0 + p;
        float4 q = {0.f, 0.f, 0.f, 0.f};
        if (s < cnt && m < MOUT) {
            const int cb = g_klist[mg * CAPB + s];
            q = *reinterpret_cast<const float4*>(W + (size_t)m * KTOT + (size_t)cb * 4);
        }
        v[p * 4 + 0] = q.x; v[p * 4 + 1] = q.y; v[p * 4 + 2] = q.z; v[p * 4 + 3] = q.w;
    }
    __half h[8];
#pragma unroll
    for (int u = 0; u < 8; u++) h[u] = __float2half_rn(v[u]);

    uint32_t off = (uint32_t)(row * 128 + (tid & 7) * 16);
    off ^= (off >> 3) & 0x70;
    char* dst = reinterpret_cast<char*>(g_Wc) + ((size_t)(mg * NCHMAX + c)) * 4096 + off;
    *reinterpret_cast<uint4*>(dst) = *reinterpret_cast<uint4*>(h);
}

// ---------------- K3: X fp32 [K,2000] -> g_Xn fp16 [K,2048] ----------------
__global__ void __launch_bounds__(256) fill_xn_kernel(const float* __restrict__ X) {
    const int k = blockIdx.x;
    const int n0 = threadIdx.x * 8;
    __half h[8];
    if (n0 + 8 <= NOUT) {
        const float4 a = *reinterpret_cast<const float4*>(X + (size_t)k * NOUT + n0);
        const float4 b = *reinterpret_cast<const float4*>(X + (size_t)k * NOUT + n0 + 4);
        h[0] = __float2half_rn(a.x); h[1] = __float2half_rn(a.y);
        h[2] = __float2half_rn(a.z); h[3] = __float2half_rn(a.w);
        h[4] = __float2half_rn(b.x); h[5] = __float2half_rn(b.y);
        h[6] = __float2half_rn(b.z); h[7] = __float2half_rn(b.w);
    } else {
#pragma unroll
        for (int u = 0; u < 8; u++) {
            int n = n0 + u;
            h[u] = __float2half_rn(n < NOUT ? X[(size_t)k * NOUT + n] : 0.0f);
        }
    }
    *reinterpret_cast<uint4*>(g_Xn + (size_t)k * NPAD + n0) = *reinterpret_cast<uint4*>(h);
}

// ---------------- K4: sparse GEMM ----------------
// Tile = (mg, nt): out rows [mg*32, +32) x cols [nt*256, +256), full compacted K.
// A: Wc chunks (pre-swizzled, linear copy). B: gathered Xn k-rows (512B slices),
// consumed via ldmatrix.trans. Work-stealing over 512 tiles.
__global__ void __launch_bounds__(256, 2)
gemm_sparse_kernel(const float* __restrict__ W_unused, const float* __restrict__ bias,
                   float* __restrict__ out) {
    extern __shared__ char sm[];
    const uint32_t sb = smem_u32(sm);
    __shared__ int sTile;
    const int tid = threadIdx.x;
    const int lane = tid & 31;
    const int wn = tid >> 5;          // 8 warps over N, 32 cols each; all warps cover 32 M rows

    // DMA addressing constants
    const int brow = tid >> 2;                         // 0..63 (B k-row)
    const uint32_t bnd_base = (uint32_t)((tid & 3) * 128);
    const uint32_t bnd_xor = (uint32_t)((brow & 7) << 4);

    // compute addressing constants
    const int fr = lane & 15;
    const int kh = lane >> 4;
    const uint32_t sXor = (uint32_t)((fr & 7) << 4);
    const uint32_t kSel = (uint32_t)(kh * 16);
    const uint32_t aRow0 = (uint32_t)(fr * 128);          // f=0
    const uint32_t aRow1 = (uint32_t)((16 + fr) * 128);   // f=1
    // B trans-ldsm lane constants: k-part (bits >=9) and n-part (bits [8:4])
    const uint32_t bK = (uint32_t)(((((lane >> 4) & 1) * 8) + (lane & 7)) * 512);
    const uint32_t bXor = (uint32_t)((lane & 7) << 4);
    const uint32_t bN0 = ((uint32_t)(wn * 64 + ((lane >> 3) & 1) * 16)) ^ bXor;        // h=0
    const uint32_t bN1 = ((uint32_t)(wn * 64 + 32 + ((lane >> 3) & 1) * 16)) ^ bXor;   // h=1

    const int mw0 = lane >> 2;
    const int nw0 = wn * 32 + (lane & 3) * 2;

    while (true) {
        __syncthreads();
        if (tid == 0) sTile = atomicAdd(&g_ctr, 1);
        __syncthreads();
        const int tile = sTile;
        if (tile >= NTILE_TOT) break;
        const int mg = tile >> 3;
        const int nt = tile & 7;
        const int nch = g_nch[mg];
        if (nch == 0) continue;

        const char* WcBase = reinterpret_cast<const char*>(g_Wc) + (size_t)(mg * NCHMAX) * 4096;
        const int* kl = g_klist + mg * CAPB;
        const size_t xnSliceB = (size_t)nt * 512;   // byte offset of n-slice in an Xn row

        auto issue = [&](int c, int s) {
            const uint32_t sA = sb + (uint32_t)s * STG_BYTES;
            const uint32_t sB = sA + A_ST;
            // A chunk: 4KB linear
            cp16(sA + (uint32_t)(tid * 16), WcBase + (size_t)c * 4096 + tid * 16);
            // B: 64 gathered k-rows x 512B
            const int cb = kl[c * 16 + (tid >> 4)];
            const int gk = cb * 4 + (brow & 3);
            const char* src = reinterpret_cast<const char*>(g_Xn)
                              + (size_t)gk * (NPAD * 2) + xnSliceB + (tid & 3) * 128;
            const uint32_t dRow = sB + (uint32_t)(brow * 512);
#pragma unroll
            for (int i = 0; i < 8; i++) {
                const uint32_t nd = (bnd_base + (uint32_t)(i * 16)) ^ bnd_xor;
                cp16(dRow + nd, src + i * 16);
            }
        };

        float acc[2][4][4];
#pragma unroll
        for (int f = 0; f < 2; f++)
#pragma unroll
            for (int j = 0; j < 4; j++)
#pragma unroll
                for (int e = 0; e < 4; e++) acc[f][j][e] = 0.0f;

        // prologue
        issue(0, 0);
        cp_commit();
        if (nch > 1) issue(1, 1);
        cp_commit();

#pragma unroll 1
        for (int c = 0; c < nch; c++) {
            cp_wait<1>();
            __syncthreads();
            if (c + 2 < nch) issue(c + 2, (c + 2) % STAGES);
            cp_commit();

            const uint32_t sA = sb + (uint32_t)(c % STAGES) * STG_BYTES;
            const uint32_t sB = sA + A_ST;

#pragma unroll
            for (int ks = 0; ks < 4; ks++) {
                const uint32_t kc = ((uint32_t)(ks * 32) + kSel) ^ sXor;
                uint32_t af[2][4];
                ldsm_x4(af[0], sA + aRow0 + kc);
                ldsm_x4(af[1], sA + aRow1 + kc);

                uint32_t bn[4][2];
                {
                    uint32_t q[4];
                    ldsm_x4_t(q, sB + bK + (uint32_t)(ks * 8192) + bN0);
                    bn[0][0] = q[0]; bn[1][0] = q[1]; bn[0][1] = q[2]; bn[1][1] = q[3];
                    ldsm_x4_t(q, sB + bK + (uint32_t)(ks * 8192) + bN1);
                    bn[2][0] = q[0]; bn[3][0] = q[1]; bn[2][1] = q[2]; bn[3][1] = q[3];
                }
#pragma unroll
                for (int f = 0; f < 2; f++)
#pragma unroll
                    for (int j = 0; j < 4; j++)
                        mma16816(acc[f][j], af[f], bn[j]);
            }
        }

        // epilogue: direct store with bias (each out element owned by exactly one tile)
        {
            const int mB = mg * GR + mw0;
            const int nB = nt * BN + nw0;
#pragma unroll
            for (int f = 0; f < 2; f++) {
                const int m_a = mB + f * 16;
                const int m_b = m_a + 8;
#pragma unroll
                for (int j = 0; j < 4; j++) {
                    const int n = nB + j * 8;
                    if (n < NOUT) {
                        const float2 bb = *reinterpret_cast<const float2*>(bias + n);
                        if (m_a < MOUT) {
                            float2 v = {acc[f][j][0] + bb.x, acc[f][j][1] + bb.y};
                            *reinterpret_cast<float2*>(out + (size_t)m_a * NOUT + n) = v;
                        }
                        if (m_b < MOUT) {
                            float2 v = {acc[f][j][2] + bb.x, acc[f][j][3] + bb.y};
                            *reinterpret_cast<float2*>(out + (size_t)m_b * NOUT + n) = v;
                        }
                    }
                }
            }
        }
    }
}

// ---------------- launch ----------------
extern "C" void kernel_launch(void* const* d_in, const int* in_sizes, int n_in,
                              void* d_out, int out_size) {
    const float* W    = (const float*)d_in[0];   // [2000, 8192]
    const float* bias = (const float*)d_in[1];   // [2000]
    const float* X    = (const float*)d_in[2];   // [8192, 2000]
    float* out        = (float*)d_out;           // [2000, 2000]

    (void)in_sizes; (void)n_in; (void)out_size;

    build_klist_kernel<<<NGRP, 256>>>(W);                    // also resets g_ctr
    fill_wc_kernel<<<dim3(NCHMAX, NGRP), 256>>>(W);
    fill_xn_kernel<<<KTOT, 256>>>(X);

    int nsm = 148;
    cudaDeviceGetAttribute(&nsm, cudaDevAttrMultiProcessorCount, 0);
    cudaFuncSetAttribute(gemm_sparse_kernel,
                         cudaFuncAttributeMaxDynamicSharedMemorySize, SMEM_TOTAL);
    gemm_sparse_kernel<<<2 * nsm, 256, SMEM_TOTAL>>>(W, bias, out);
}

// round 12
// speedup vs baseline: 2.4077x; 2.4077x over previous
#include <cuda_runtime.h>
#include <cuda_fp16.h>
#include <cstdint>

// Problem dims
#define KTOT 8192
#define MPAD 2048
#define NPAD 2048
#define MOUT 2000
#define NOUT 2000

// GEMM tiling: 128x128 tiles, 2 CTAs per SM
#define BM 128
#define BN 128
#define BK 64
#define STAGES 3
#define CHUNKS 128
#define TILES_M (MPAD / BM)         // 16
#define TILES_N (NPAD / BN)         // 16
#define NTILES (TILES_M * TILES_N)  // 256
#define TOTALG (NTILES * CHUNKS)    // 32768

#define A_STAGE_BYTES (BM * BK * 2)   // 16 KB
#define B_STAGE_BYTES (BN * BK * 2)   // 16 KB
#define STAGE_BYTES (A_STAGE_BYTES + B_STAGE_BYTES)  // 32 KB
#define SMEM_TOTAL (STAGES * STAGE_BYTES)            // 96 KB

__device__ __half g_Wh[(size_t)MPAD * KTOT];
__device__ __half g_XT[(size_t)NPAD * KTOT];

// ---------------- PTX helpers ----------------
__device__ __forceinline__ uint32_t smem_u32(const void* p) {
    uint32_t a;
    asm("{ .reg .u64 t; cvta.to.shared.u64 t, %1; cvt.u32.u64 %0, t; }" : "=r"(a) : "l"(p));
    return a;
}

__device__ __forceinline__ void cp16(uint32_t s, const void* g) {
    asm volatile("cp.async.cg.shared.global [%0], [%1], 16;" :: "r"(s), "l"(g));
}

__device__ __forceinline__ void cp_commit() {
    asm volatile("cp.async.commit_group;" ::: "memory");
}

template <int N>
__device__ __forceinline__ void cp_wait() {
    asm volatile("cp.async.wait_group %0;" :: "n"(N) : "memory");
}

__device__ __forceinline__ void ldsm_x4(uint32_t* r, uint32_t addr) {
    asm volatile("ldmatrix.sync.aligned.m8n8.x4.shared.b16 {%0,%1,%2,%3}, [%4];"
                 : "=r"(r[0]), "=r"(r[1]), "=r"(r[2]), "=r"(r[3]) : "r"(addr));
}

__device__ __forceinline__ void mma16816(float* c, const uint32_t* a, const uint32_t* b) {
    asm volatile(
        "mma.sync.aligned.m16n8k16.row.col.f32.f16.f16.f32 "
        "{%0,%1,%2,%3}, {%4,%5,%6,%7}, {%8,%9}, {%0,%1,%2,%3};"
        : "+f"(c[0]), "+f"(c[1]), "+f"(c[2]), "+f"(c[3])
        : "r"(a[0]), "r"(a[1]), "r"(a[2]), "r"(a[3]), "r"(b[0]), "r"(b[1]));
}

// ---------------- Init: out[m][n] = bias[n] ----------------
__global__ void __launch_bounds__(512) init_out_kernel(const float* __restrict__ bias,
                                                       float* __restrict__ out) {
    int n = blockIdx.x * blockDim.x + threadIdx.x;
    int m = blockIdx.y;
    if (n < NOUT) out[(size_t)m * NOUT + n] = bias[n];
}

// ---------------- Conversion kernels ----------------
__global__ void __launch_bounds__(256) convert_w_kernel(const float* __restrict__ W) {
    size_t t = (size_t)blockIdx.x * blockDim.x + threadIdx.x;
    size_t idx4 = t * 4;
    if (idx4 >= (size_t)MPAD * KTOT) return;
    int row = (int)(idx4 >> 13);
    __half2* ph = reinterpret_cast<__half2*>(&g_Wh[idx4]);
    if (row < MOUT) {
        float4 v = *reinterpret_cast<const float4*>(W + idx4);
        ph[0] = __halves2half2(__float2half_rn(v.x), __float2half_rn(v.y));
        ph[1] = __halves2half2(__float2half_rn(v.z), __float2half_rn(v.w));
    } else {
        __half2 z = __float2half2_rn(0.0f);
        ph[0] = z; ph[1] = z;
    }
}

// X [8192,2000] fp32 -> g_XT [2048,8192] fp16 K-major.
// Tile 64(k) x 32(n); write phase emits full 128B rows (uint32 per thread).
__global__ void __launch_bounds__(256) convert_x_kernel(const float* __restrict__ X) {
    __shared__ float tile[64][33];
    const int kb = blockIdx.x * 64;
    const int nb = blockIdx.y * 32;
    const int tx = threadIdx.x & 31;
    const int ty = threadIdx.x >> 5;   // 0..7

    // load: 64 k-rows, 32 n-cols; coalesced 128B reads per row
#pragma unroll
    for (int r = 0; r < 64; r += 8) {
        const int k = kb + ty + r;
        const int n = nb + tx;
        tile[ty + r][tx] = (n < NOUT) ? X[(size_t)k * NOUT + n] : 0.0f;
    }
    __syncthreads();

    // write: each warp emits one n-row of 64 halfs (128B) per iteration
#pragma unroll
    for (int it = 0; it < 4; it++) {
        const int nloc = ty + it * 8;        // 0..31
        const int n = nb + nloc;
        const int k0 = 2 * tx;
        __half2 v = __halves2half2(__float2half_rn(tile[k0][nloc]),
                                   __float2half_rn(tile[k0 + 1][nloc]));
        *reinterpret_cast<__half2*>(g_XT + (size_t)n * KTOT + kb + k0) = v;
    }
}

// ---------------- Persistent GEMM kernel: 2 CTAs/SM, 128x128 tiles ----------
// Work unit g in [0, TOTALG): tile t = g>>7 (tm = t&15 -> M, tn = t>>4 -> N),
// K-chunk c = g&127. CTA j covers [j*TOTALG/ncta, (j+1)*TOTALG/ncta).
__global__ void __launch_bounds__(256, 2)
gemm_persist_kernel(float* __restrict__ out) {
    extern __shared__ char sm[];
    const uint32_t sb = smem_u32(sm);
    const int tid = threadIdx.x;
    const int lane = tid & 31;
    const int wid = tid >> 5;
    const int warp_m = wid & 1;     // 2 warps over M (64 rows each)
    const int warp_n = wid >> 1;    // 4 warps over N (32 cols each)

    const int ncta = gridDim.x;
    const int g0 = (int)(((long long)blockIdx.x * TOTALG) / ncta);
    const int g1 = (int)(((long long)(blockIdx.x + 1) * TOTALG) / ncta);

    const int lrow = tid >> 3;      // 0..31
    const int lcol = tid & 7;
    uint32_t st_off[4];
#pragma unroll
    for (int j = 0; j < 4; j++) {
        uint32_t off = (uint32_t)((lrow + 32 * j) * 128 + lcol * 16);
        st_off[j] = off ^ ((off >> 3) & 0x70);
    }

    auto issue_loads = [&](int g, int s) {
        const int t = g >> 7;
        const int c = g & 127;
        const __half* Ab = g_Wh + ((size_t)(t & 15) << 7) * KTOT + (size_t)c * 64 + lcol * 8;
        const __half* Bb = g_XT + ((size_t)(t >> 4) << 7) * KTOT + (size_t)c * 64 + lcol * 8;
        uint32_t sA = sb + (uint32_t)s * STAGE_BYTES;
        uint32_t sB = sA + A_STAGE_BYTES;
#pragma unroll
        for (int j = 0; j < 4; j++)
            cp16(sA + st_off[j], Ab + (size_t)(lrow + 32 * j) * KTOT);
#pragma unroll
        for (int j = 0; j < 4; j++)
            cp16(sB + st_off[j], Bb + (size_t)(lrow + 32 * j) * KTOT);
    };

    // prologue
    issue_loads(g0, 0);
    cp_commit();
    issue_loads(g0 + 1, 1);
    cp_commit();

    const int fr = lane & 15;
    const int kh = lane >> 4;
    const uint32_t aRow = (uint32_t)((warp_m * 64 + fr) * 128);
    const uint32_t bRow = (uint32_t)((warp_n * 32 + fr) * 128);
    const uint32_t sXor = (uint32_t)((fr & 7) << 4);
    const uint32_t kSel = (uint32_t)(kh * 16);

    const int mw0 = warp_m * 64 + (lane >> 2);
    const int nw0 = warp_n * 32 + (lane & 3) * 2;

    float acc[4][4][4];

    int g = g0;
    int cs = 0;
    int ps = STAGES - 1;
    while (g < g1) {
        const int segEnd = min(g1, ((g >> 7) + 1) << 7);
        const int segTile = g >> 7;

#pragma unroll
        for (int f = 0; f < 4; f++)
#pragma unroll
            for (int j = 0; j < 4; j++)
#pragma unroll
                for (int e = 0; e < 4; e++) acc[f][j][e] = 0.0f;

#pragma unroll 1
        for (; g < segEnd; g++) {
            cp_wait<STAGES - 2>();
            __syncthreads();

            const int pg = g + STAGES - 1;
            if (pg < g1) issue_loads(pg, ps);
            cp_commit();

            const uint32_t sA = sb + (uint32_t)cs * STAGE_BYTES;
            const uint32_t sB = sA + A_STAGE_BYTES;
            const uint32_t aBase = sA + aRow;
            const uint32_t bBase = sB + bRow;

#pragma unroll
            for (int ks = 0; ks < 4; ks++) {
                const uint32_t kc = ((uint32_t)(ks * 32) + kSel) ^ sXor;
                uint32_t af[4][4];
#pragma unroll
                for (int f = 0; f < 4; f++)
                    ldsm_x4(af[f], aBase + (uint32_t)(f * 2048) + kc);
                uint32_t bn[4][2];
#pragma unroll
                for (int t = 0; t < 2; t++) {
                    uint32_t r[4];
                    ldsm_x4(r, bBase + (uint32_t)(t * 2048) + kc);
                    bn[2 * t][0] = r[0];
                    bn[2 * t + 1][0] = r[1];
                    bn[2 * t][1] = r[2];
                    bn[2 * t + 1][1] = r[3];
                }
#pragma unroll
                for (int f = 0; f < 4; f++)
#pragma unroll
                    for (int j = 0; j < 4; j++)
                        mma16816(acc[f][j], af[f], bn[j]);
            }

            if (++cs == STAGES) cs = 0;
            if (++ps == STAGES) ps = 0;
        }

        // segment epilogue: RED-add partial tile
        {
            const int m0 = (segTile & 15) << 7;
            const int n0 = (segTile >> 4) << 7;
#pragma unroll
            for (int f = 0; f < 4; f++) {
                int m_a = m0 + mw0 + f * 16;
                int m_b = m_a + 8;
#pragma unroll
                for (int j = 0; j < 4; j++) {
                    int n = n0 + nw0 + j * 8;
                    if (n < NOUT) {
                        if (m_a < MOUT) {
                            atomicAdd(out + (size_t)m_a * NOUT + n,     acc[f][j][0]);
                            atomicAdd(out + (size_t)m_a * NOUT + n + 1, acc[f][j][1]);
                        }
                        if (m_b < MOUT) {
                            atomicAdd(out + (size_t)m_b * NOUT + n,     acc[f][j][2]);
                            atomicAdd(out + (size_t)m_b * NOUT + n + 1, acc[f][j][3]);
                        }
                    }
                }
            }
        }
    }
}

// ---------------- launch ----------------
extern "C" void kernel_launch(void* const* d_in, const int* in_sizes, int n_in,
                              void* d_out, int out_size) {
    const float* W    = (const float*)d_in[0];
    const float* bias = (const float*)d_in[1];
    const float* X    = (const float*)d_in[2];
    float* out        = (float*)d_out;

    (void)in_sizes; (void)n_in; (void)out_size;

    {   // out = bias broadcast
        dim3 grid((NOUT + 511) / 512, MOUT);
        init_out_kernel<<<grid, 512>>>(bias, out);
    }
    {   // W -> fp16
        size_t quads = (size_t)MPAD * KTOT / 4;
        int blocks = (int)((quads + 255) / 256);
        convert_w_kernel<<<blocks, 256>>>(W);
    }
    {   // X transpose to fp16 K-major (128B-row writes)
        dim3 grid(KTOT / 64, NPAD / 32);
        convert_x_kernel<<<grid, 256>>>(X);
    }

    int nsm = 148;
    cudaDeviceGetAttribute(&nsm, cudaDevAttrMultiProcessorCount, 0);
    cudaFuncSetAttribute(gemm_persist_kernel,
                         cudaFuncAttributeMaxDynamicSharedMemorySize, SMEM_TOTAL);
    gemm_persist_kernel<<<2 * nsm, 256, SMEM_TOTAL>>>(out);
}

// round 13
// speedup vs baseline: 2.4754x; 1.0281x over previous
#include <cuda_runtime.h>
#include <cuda_fp16.h>
#include <cstdint>

// Problem dims
#define KTOT 8192
#define MPAD 2048
#define NPAD 2048
#define MOUT 2000
#define NOUT 2000

// GEMM tiling: 128x128 tiles, 2 CTAs per SM
#define BM 128
#define BN 128
#define BK 64
#define STAGES 3
#define CHUNKS 128
#define TILES_M (MPAD / BM)         // 16
#define TILES_N (NPAD / BN)         // 16
#define NTILES (TILES_M * TILES_N)  // 256
#define TOTALG (NTILES * CHUNKS)    // 32768

#define A_STAGE_BYTES (BM * BK * 2)   // 16 KB
#define B_STAGE_BYTES (BN * BK * 2)   // 16 KB
#define STAGE_BYTES (A_STAGE_BYTES + B_STAGE_BYTES)  // 32 KB
#define SMEM_TOTAL (STAGES * STAGE_BYTES)            // 96 KB

// Fused pre-kernel block partition
#define NB_W 16384                   // convert_w blocks
#define NB_X 8192                    // convert_x blocks (128 k-tiles x 64 n-tiles)
#define NB_INIT 3907                 // init blocks (1,000,000 float4 / 256)
#define NB_PRE (NB_W + NB_X + NB_INIT)

__device__ __half g_Wh[(size_t)MPAD * KTOT];
__device__ __half g_XT[(size_t)NPAD * KTOT];

// ---------------- PTX helpers ----------------
__device__ __forceinline__ uint32_t smem_u32(const void* p) {
    uint32_t a;
    asm("{ .reg .u64 t; cvta.to.shared.u64 t, %1; cvt.u32.u64 %0, t; }" : "=r"(a) : "l"(p));
    return a;
}

__device__ __forceinline__ void cp16(uint32_t s, const void* g) {
    asm volatile("cp.async.cg.shared.global [%0], [%1], 16;" :: "r"(s), "l"(g));
}

__device__ __forceinline__ void cp_commit() {
    asm volatile("cp.async.commit_group;" ::: "memory");
}

template <int N>
__device__ __forceinline__ void cp_wait() {
    asm volatile("cp.async.wait_group %0;" :: "n"(N) : "memory");
}

__device__ __forceinline__ void ldsm_x4(uint32_t* r, uint32_t addr) {
    asm volatile("ldmatrix.sync.aligned.m8n8.x4.shared.b16 {%0,%1,%2,%3}, [%4];"
                 : "=r"(r[0]), "=r"(r[1]), "=r"(r[2]), "=r"(r[3]) : "r"(addr));
}

__device__ __forceinline__ void mma16816(float* c, const uint32_t* a, const uint32_t* b) {
    asm volatile(
        "mma.sync.aligned.m16n8k16.row.col.f32.f16.f16.f32 "
        "{%0,%1,%2,%3}, {%4,%5,%6,%7}, {%8,%9}, {%0,%1,%2,%3};"
        : "+f"(c[0]), "+f"(c[1]), "+f"(c[2]), "+f"(c[3])
        : "r"(a[0]), "r"(a[1]), "r"(a[2]), "r"(a[3]), "r"(b[0]), "r"(b[1]));
}

// ---------------- Fused pre-kernel: convert_w | convert_x | init_out ------
__global__ void __launch_bounds__(256) prep_kernel(const float* __restrict__ W,
                                                   const float* __restrict__ X,
                                                   const float* __restrict__ bias,
                                                   float* __restrict__ out) {
    const int b = blockIdx.x;

    if (b < NB_W) {
        // ---- convert_w: W [2000,8192] fp32 -> g_Wh [2048,8192] fp16 ----
        size_t t = (size_t)b * 256 + threadIdx.x;
        size_t idx4 = t * 4;
        int row = (int)(idx4 >> 13);
        __half2* ph = reinterpret_cast<__half2*>(&g_Wh[idx4]);
        if (row < MOUT) {
            float4 v = *reinterpret_cast<const float4*>(W + idx4);
            ph[0] = __halves2half2(__float2half_rn(v.x), __float2half_rn(v.y));
            ph[1] = __halves2half2(__float2half_rn(v.z), __float2half_rn(v.w));
        } else {
            __half2 z = __float2half2_rn(0.0f);
            ph[0] = z; ph[1] = z;
        }
    } else if (b < NB_W + NB_X) {
        // ---- convert_x: X [8192,2000] fp32 -> g_XT [2048,8192] fp16 K-major ----
        __shared__ float tile[64][33];
        const int id = b - NB_W;
        const int kb = (id & 127) * 64;       // 128 k-tiles
        const int nb = (id >> 7) * 32;        // 64 n-tiles
        const int tx = threadIdx.x & 31;
        const int ty = threadIdx.x >> 5;      // 0..7

#pragma unroll
        for (int r = 0; r < 64; r += 8) {
            const int k = kb + ty + r;
            const int n = nb + tx;
            tile[ty + r][tx] = (n < NOUT) ? X[(size_t)k * NOUT + n] : 0.0f;
        }
        __syncthreads();

#pragma unroll
        for (int it = 0; it < 4; it++) {
            const int nloc = ty + it * 8;
            const int n = nb + nloc;
            const int k0 = 2 * tx;
            __half2 v = __halves2half2(__float2half_rn(tile[k0][nloc]),
                                       __float2half_rn(tile[k0 + 1][nloc]));
            *reinterpret_cast<__half2*>(g_XT + (size_t)n * KTOT + kb + k0) = v;
        }
    } else {
        // ---- init_out: out[m][n] = bias[n], float4 granularity ----
        const int q = (b - NB_W - NB_X) * 256 + threadIdx.x;   // 0 .. 1,000,000
        if (q < (MOUT * NOUT) / 4) {
            const int row = q / (NOUT / 4);
            const int c4 = q % (NOUT / 4);
            const float4 v = *reinterpret_cast<const float4*>(bias + c4 * 4);
            *reinterpret_cast<float4*>(out + (size_t)row * NOUT + c4 * 4) = v;
        }
    }
}

// ---------------- Persistent GEMM kernel: 2 CTAs/SM, 128x128 tiles ----------
// (unchanged from round 12 — known-good 185 us)
__global__ void __launch_bounds__(256, 2)
gemm_persist_kernel(float* __restrict__ out) {
    extern __shared__ char sm[];
    const uint32_t sb = smem_u32(sm);
    const int tid = threadIdx.x;
    const int lane = tid & 31;
    const int wid = tid >> 5;
    const int warp_m = wid & 1;     // 2 warps over M (64 rows each)
    const int warp_n = wid >> 1;    // 4 warps over N (32 cols each)

    const int ncta = gridDim.x;
    const int g0 = (int)(((long long)blockIdx.x * TOTALG) / ncta);
    const int g1 = (int)(((long long)(blockIdx.x + 1) * TOTALG) / ncta);

    const int lrow = tid >> 3;      // 0..31
    const int lcol = tid & 7;
    uint32_t st_off[4];
#pragma unroll
    for (int j = 0; j < 4; j++) {
        uint32_t off = (uint32_t)((lrow + 32 * j) * 128 + lcol * 16);
        st_off[j] = off ^ ((off >> 3) & 0x70);
    }

    auto issue_loads = [&](int g, int s) {
        const int t = g >> 7;
        const int c = g & 127;
        const __half* Ab = g_Wh + ((size_t)(t & 15) << 7) * KTOT + (size_t)c * 64 + lcol * 8;
        const __half* Bb = g_XT + ((size_t)(t >> 4) << 7) * KTOT + (size_t)c * 64 + lcol * 8;
        uint32_t sA = sb + (uint32_t)s * STAGE_BYTES;
        uint32_t sB = sA + A_STAGE_BYTES;
#pragma unroll
        for (int j = 0; j < 4; j++)
            cp16(sA + st_off[j], Ab + (size_t)(lrow + 32 * j) * KTOT);
#pragma unroll
        for (int j = 0; j < 4; j++)
            cp16(sB + st_off[j], Bb + (size_t)(lrow + 32 * j) * KTOT);
    };

    // prologue
    issue_loads(g0, 0);
    cp_commit();
    issue_loads(g0 + 1, 1);
    cp_commit();

    const int fr = lane & 15;
    const int kh = lane >> 4;
    const uint32_t aRow = (uint32_t)((warp_m * 64 + fr) * 128);
    const uint32_t bRow = (uint32_t)((warp_n * 32 + fr) * 128);
    const uint32_t sXor = (uint32_t)((fr & 7) << 4);
    const uint32_t kSel = (uint32_t)(kh * 16);

    const int mw0 = warp_m * 64 + (lane >> 2);
    const int nw0 = warp_n * 32 + (lane & 3) * 2;

    float acc[4][4][4];

    int g = g0;
    int cs = 0;
    int ps = STAGES - 1;
    while (g < g1) {
        const int segEnd = min(g1, ((g >> 7) + 1) << 7);
        const int segTile = g >> 7;

#pragma unroll
        for (int f = 0; f < 4; f++)
#pragma unroll
            for (int j = 0; j < 4; j++)
#pragma unroll
                for (int e = 0; e < 4; e++) acc[f][j][e] = 0.0f;

#pragma unroll 1
        for (; g < segEnd; g++) {
            cp_wait<STAGES - 2>();
            __syncthreads();

            const int pg = g + STAGES - 1;
            if (pg < g1) issue_loads(pg, ps);
            cp_commit();

            const uint32_t sA = sb + (uint32_t)cs * STAGE_BYTES;
            const uint32_t sB = sA + A_STAGE_BYTES;
            const uint32_t aBase = sA + aRow;
            const uint32_t bBase = sB + bRow;

#pragma unroll
            for (int ks = 0; ks < 4; ks++) {
                const uint32_t kc = ((uint32_t)(ks * 32) + kSel) ^ sXor;
                uint32_t af[4][4];
#pragma unroll
                for (int f = 0; f < 4; f++)
                    ldsm_x4(af[f], aBase + (uint32_t)(f * 2048) + kc);
                uint32_t bn[4][2];
#pragma unroll
                for (int t = 0; t < 2; t++) {
                    uint32_t r[4];
                    ldsm_x4(r, bBase + (uint32_t)(t * 2048) + kc);
                    bn[2 * t][0] = r[0];
                    bn[2 * t + 1][0] = r[1];
                    bn[2 * t][1] = r[2];
                    bn[2 * t + 1][1] = r[3];
                }
#pragma unroll
                for (int f = 0; f < 4; f++)
#pragma unroll
                    for (int j = 0; j < 4; j++)
                        mma16816(acc[f][j], af[f], bn[j]);
            }

            if (++cs == STAGES) cs = 0;
            if (++ps == STAGES) ps = 0;
        }

        // segment epilogue: RED-add partial tile
        {
            const int m0 = (segTile & 15) << 7;
            const int n0 = (segTile >> 4) << 7;
#pragma unroll
            for (int f = 0; f < 4; f++) {
                int m_a = m0 + mw0 + f * 16;
                int m_b = m_a + 8;
#pragma unroll
                for (int j = 0; j < 4; j++) {
                    int n = n0 + nw0 + j * 8;
                    if (n < NOUT) {
                        if (m_a < MOUT) {
                            atomicAdd(out + (size_t)m_a * NOUT + n,     acc[f][j][0]);
                            atomicAdd(out + (size_t)m_a * NOUT + n + 1, acc[f][j][1]);
                        }
                        if (m_b < MOUT) {
                            atomicAdd(out + (size_t)m_b * NOUT + n,     acc[f][j][2]);
                            atomicAdd(out + (size_t)m_b * NOUT + n + 1, acc[f][j][3]);
                        }
                    }
                }
            }
        }
    }
}

// ---------------- launch ----------------
extern "C" void kernel_launch(void* const* d_in, const int* in_sizes, int n_in,
                              void* d_out, int out_size) {
    const float* W    = (const float*)d_in[0];
    const float* bias = (const float*)d_in[1];
    const float* X    = (const float*)d_in[2];
    float* out        = (float*)d_out;

    (void)in_sizes; (void)n_in; (void)out_size;

    prep_kernel<<<NB_PRE, 256>>>(W, X, bias, out);

    int nsm = 148;
    cudaDeviceGetAttribute(&nsm, cudaDevAttrMultiProcessorCount, 0);
    cudaFuncSetAttribute(gemm_persist_kernel,
                         cudaFuncAttributeMaxDynamicSharedMemorySize, SMEM_TOTAL);
    gemm_persist_kernel<<<2 * nsm, 256, SMEM_TOTAL>>>(out);
}